// round 1
// baseline (speedup 1.0000x reference)
#include <cuda_runtime.h>
#include <cstddef>

#define N_NODE 10000
#define N_INST 50000
#define N_SVC  20000
#define NEDGE  200000
#define D      128
#define NREL   6
#define MAXN   50000
#define TOTAL_DST_ROWS 200000  // 20000+10000+50000+50000+50000+20000

// Scratch (static device allocations are allowed; no cudaMalloc).
__device__ float g_agg[(size_t)TOTAL_DST_ROWS * D];   // ~102.4 MB
__device__ float g_deg_out[NREL][MAXN];
__device__ float g_deg_in[NREL][MAXN];

// ---------------------------------------------------------------------------
// Zero scratch: agg buffer + degree arrays.
__global__ void zero_all_kernel() {
    size_t i = (size_t)blockIdx.x * blockDim.x + threadIdx.x;
    size_t stride = (size_t)gridDim.x * blockDim.x;
    float4* a = reinterpret_cast<float4*>(g_agg);
    const size_t n4 = (size_t)TOTAL_DST_ROWS * D / 4;
    for (size_t j = i; j < n4; j += stride) a[j] = make_float4(0.f, 0.f, 0.f, 0.f);
    float* d0 = &g_deg_out[0][0];
    float* d1 = &g_deg_in[0][0];
    const size_t nd = (size_t)NREL * MAXN;
    for (size_t j = i; j < nd; j += stride) { d0[j] = 0.f; d1[j] = 0.f; }
}

// ---------------------------------------------------------------------------
// Per-relation degree histogram.
__global__ void degree_kernel(const int* __restrict__ src, const int* __restrict__ dst,
                              int rel, int n) {
    int i = blockIdx.x * blockDim.x + threadIdx.x;
    if (i < n) {
        atomicAdd(&g_deg_out[rel][src[i]], 1.f);
        atomicAdd(&g_deg_in[rel][dst[i]], 1.f);
    }
}

// ---------------------------------------------------------------------------
// Scatter-aggregate: one warp per edge; agg[dst] += X[src] * rsqrt(max(out_deg[src],1)).
// Uses vectorized red.global.add.v4.f32 (sm_90+) -> 32 RED ops per edge.
__global__ void aggregate_kernel(const float* __restrict__ X,
                                 const int* __restrict__ src,
                                 const int* __restrict__ dst,
                                 int rel, int agg_row_off, int n_edges) {
    int warp = (blockIdx.x * blockDim.x + threadIdx.x) >> 5;
    int lane = threadIdx.x & 31;
    if (warp >= n_edges) return;
    int s = src[warp];
    int d = dst[warp];
    float rs = rsqrtf(fmaxf(g_deg_out[rel][s], 1.f));
    float4 v = reinterpret_cast<const float4*>(X + (size_t)s * D)[lane];
    v.x *= rs; v.y *= rs; v.z *= rs; v.w *= rs;
    float* p = g_agg + ((size_t)(agg_row_off + d)) * D + lane * 4;
    asm volatile("red.global.add.v4.f32 [%0], {%1, %2, %3, %4};"
                 :: "l"(p), "f"(v.x), "f"(v.y), "f"(v.z), "f"(v.w)
                 : "memory");
}

// ---------------------------------------------------------------------------
// Dense GEMM [n_rows, 128] x [128, 128] with fused epilogue:
//   y = (agg @ W) * rsqrt(max(in_deg,1)) + b, then out = (FIRST? 0 : out) + y*scale,
//   optional relu on the LAST relation of each destination type.
// flags: bit0 = FIRST (overwrite), bit1 = RELU (final).
#define GEMM_ROWS 16
__global__ void gemm_epilogue_kernel(int rel, int agg_row_off,
                                     const float* __restrict__ W,
                                     const float* __restrict__ b,
                                     float* __restrict__ out,
                                     int n_rows, float scale, int flags) {
    __shared__ float sA[GEMM_ROWS * D];
    const int tid = threadIdx.x;       // 128 threads; thread = output column
    const int row0 = blockIdx.x * GEMM_ROWS;
    const float* A = g_agg + (size_t)agg_row_off * D;

    for (int i = tid; i < GEMM_ROWS * D; i += D) {
        int r = i >> 7;
        int row = row0 + r;
        sA[i] = (row < n_rows) ? A[(size_t)row * D + (i & 127)] : 0.f;
    }
    __syncthreads();

    float acc[GEMM_ROWS];
#pragma unroll
    for (int r = 0; r < GEMM_ROWS; r++) acc[r] = 0.f;

    const int c = tid;
#pragma unroll 4
    for (int k = 0; k < D; k++) {
        float w = W[k * D + c];
#pragma unroll
        for (int r = 0; r < GEMM_ROWS; r++) acc[r] += sA[r * D + k] * w;
    }

    const float bc = b[c];
#pragma unroll
    for (int r = 0; r < GEMM_ROWS; r++) {
        int row = row0 + r;
        if (row < n_rows) {
            float rs = rsqrtf(fmaxf(g_deg_in[rel][row], 1.f));
            float v = (acc[r] * rs + bc) * scale;
            float* o = out + (size_t)row * D + c;
            if (!(flags & 1)) v += *o;
            if (flags & 2) v = fmaxf(v, 0.f);
            *o = v;
        }
    }
}

// ---------------------------------------------------------------------------
extern "C" void kernel_launch(void* const* d_in, const int* in_sizes, int n_in,
                              void* d_out, int out_size) {
    const float* node_feat = (const float*)d_in[0];
    const float* inst_feat = (const float*)d_in[1];
    const float* svc_feat  = (const float*)d_in[2];

    // Relation order in inputs: sc, in, ni, ii, si, is
    const int*   e_src[NREL];
    const int*   e_dst[NREL];
    const float* W[NREL];
    const float* B[NREL];
    for (int r = 0; r < NREL; r++) {
        e_src[r] = (const int*)  d_in[3 + r * 4 + 0];
        e_dst[r] = (const int*)  d_in[3 + r * 4 + 1];
        W[r]     = (const float*)d_in[3 + r * 4 + 2];
        B[r]     = (const float*)d_in[3 + r * 4 + 3];
    }

    // Per-relation source feature & agg-buffer row offset (rows of dst space)
    const float* srcfeat[NREL] = { svc_feat, inst_feat, node_feat, inst_feat, svc_feat, inst_feat };
    const int agg_off[NREL] = { 0, 20000, 30000, 80000, 130000, 180000 };
    // n_dst per rel: sc=20000, in=10000, ni=50000, ii=50000, si=50000, is=20000

    float* out = (float*)d_out;

    // 1. zero scratch
    zero_all_kernel<<<148 * 8, 256>>>();

    // 2. degrees
    const int degBlocks = (NEDGE + 255) / 256;
    for (int r = 0; r < NREL; r++)
        degree_kernel<<<degBlocks, 256>>>(e_src[r], e_dst[r], r, NEDGE);

    // 3. scatter-aggregate (warp per edge)
    const int aggBlocks = (NEDGE * 32 + 255) / 256;
    for (int r = 0; r < NREL; r++)
        aggregate_kernel<<<aggBlocks, 256>>>(srcfeat[r], e_src[r], e_dst[r],
                                             r, agg_off[r], NEDGE);

    // 4. dense GEMM + epilogue per destination type
    // node (rows 0..9999): relation 'in' (rel=1) only
    gemm_epilogue_kernel<<<(N_NODE + GEMM_ROWS - 1) / GEMM_ROWS, D>>>(
        1, agg_off[1], W[1], B[1], out, N_NODE, 1.0f, /*FIRST|RELU*/ 3);

    // instance (rows 10000..59999): mean of ni(2), ii(3), si(4)
    float* out_inst = out + (size_t)N_NODE * D;
    const int instBlocks = (N_INST + GEMM_ROWS - 1) / GEMM_ROWS;
    gemm_epilogue_kernel<<<instBlocks, D>>>(2, agg_off[2], W[2], B[2], out_inst,
                                            N_INST, 1.0f / 3.0f, /*FIRST*/ 1);
    gemm_epilogue_kernel<<<instBlocks, D>>>(3, agg_off[3], W[3], B[3], out_inst,
                                            N_INST, 1.0f / 3.0f, 0);
    gemm_epilogue_kernel<<<instBlocks, D>>>(4, agg_off[4], W[4], B[4], out_inst,
                                            N_INST, 1.0f / 3.0f, /*RELU*/ 2);

    // svc (rows 60000..79999): mean of sc(0), is(5)
    float* out_svc = out + (size_t)(N_NODE + N_INST) * D;
    const int svcBlocks = (N_SVC + GEMM_ROWS - 1) / GEMM_ROWS;
    gemm_epilogue_kernel<<<svcBlocks, D>>>(0, agg_off[0], W[0], B[0], out_svc,
                                           N_SVC, 0.5f, /*FIRST*/ 1);
    gemm_epilogue_kernel<<<svcBlocks, D>>>(5, agg_off[5], W[5], B[5], out_svc,
                                           N_SVC, 0.5f, /*RELU*/ 2);
}

// round 2
// speedup vs baseline: 1.5633x; 1.5633x over previous
#include <cuda_runtime.h>
#include <cstddef>

#define N_NODE 10000
#define N_INST 50000
#define N_SVC  20000
#define NEDGE  200000
#define D      128
#define NREL   6
#define MAXN   50000
#define TOTAL_DST_ROWS 200000
#define CAP 128            // bucket capacity per dst row (Poisson(<=20) -> safe)
#define TILE 64            // dst rows per block in fused kernel
#define SAS 132            // sA row stride (floats): 4-aligned, bank-skewed

// Static scratch (no runtime allocation allowed).
__device__ int g_bucket[(size_t)TOTAL_DST_ROWS * CAP];  // ~102.4 MB
__device__ int g_cnt[TOTAL_DST_ROWS];                   // in-degree == fill count
__device__ int g_outdeg[NREL * MAXN];

// ---------------------------------------------------------------------------
__global__ void zero_counts_kernel() {
    int i = blockIdx.x * blockDim.x + threadIdx.x;
    int stride = gridDim.x * blockDim.x;
    for (int j = i; j < TOTAL_DST_ROWS; j += stride) g_cnt[j] = 0;
    for (int j = i; j < NREL * MAXN; j += stride) g_outdeg[j] = 0;
}

// ---------------------------------------------------------------------------
// One pass over all 6 relations: out-degree histogram + bucket fill (CSR-lite).
__global__ void build_kernel(const int* __restrict__ s0, const int* __restrict__ d0,
                             const int* __restrict__ s1, const int* __restrict__ d1,
                             const int* __restrict__ s2, const int* __restrict__ d2,
                             const int* __restrict__ s3, const int* __restrict__ d3,
                             const int* __restrict__ s4, const int* __restrict__ d4,
                             const int* __restrict__ s5, const int* __restrict__ d5) {
    int i = blockIdx.x * blockDim.x + threadIdx.x;
    if (i >= NREL * NEDGE) return;
    int rel = i / NEDGE;
    int e = i - rel * NEDGE;
    const int* sp; const int* dp; int off;
    switch (rel) {
        case 0: sp = s0; dp = d0; off = 0;      break;  // sc  -> svc dst
        case 1: sp = s1; dp = d1; off = 20000;  break;  // in  -> node dst
        case 2: sp = s2; dp = d2; off = 30000;  break;  // ni  -> inst dst
        case 3: sp = s3; dp = d3; off = 80000;  break;  // ii  -> inst dst
        case 4: sp = s4; dp = d4; off = 130000; break;  // si  -> inst dst
        default: sp = s5; dp = d5; off = 180000; break; // is  -> svc dst
    }
    int s = sp[e];
    int d = dp[e];
    atomicAdd(&g_outdeg[rel * MAXN + s], 1);
    int pos = atomicAdd(&g_cnt[off + d], 1);
    if (pos < CAP) g_bucket[(size_t)(off + d) * CAP + pos] = s;
}

// ---------------------------------------------------------------------------
// Fused gather + GEMM + epilogue per relation.
//   agg[row] = sum_{e: dst=row} X[src_e] * rsqrt(max(outdeg[src_e],1))   (gather, smem)
//   y[row]   = (agg[row] @ W) * rsqrt(max(indeg[row],1)) + b
//   out[row] = relu?( (FIRST?0:out[row]) + y*scale )
// Block: 256 threads, TILE=64 rows. smem: W (64KB) + sA (64*SAS floats).
// flags: bit0 = FIRST (overwrite out), bit1 = RELU (final write for region).
__global__ void gconv_fused_kernel(const float* __restrict__ X,
                                   const float* __restrict__ W,
                                   const float* __restrict__ bias,
                                   float* __restrict__ out,
                                   int rel, int row_off, int n_rows,
                                   float scale, int flags) {
    extern __shared__ float sh[];
    float* sW = sh;                 // [128*128]
    float* sA = sh + D * D;         // [TILE * SAS]

    const int tid = threadIdx.x;
    const int row0 = blockIdx.x * TILE;

    // Stage W into smem: 16384 floats = 4096 float4, 16 per thread.
    {
        const float4* W4 = (const float4*)W;
        float4* sW4 = (float4*)sW;
#pragma unroll
        for (int i = 0; i < 16; i++) sW4[tid + i * 256] = W4[tid + i * 256];
    }

    // ---- Gather phase: warp per row, 8 rows per warp ----
    const int warp = tid >> 5, lane = tid & 31;
#pragma unroll 1
    for (int rr = 0; rr < 8; rr++) {
        int r = warp * 8 + rr;
        int row = row0 + r;
        float4 acc = make_float4(0.f, 0.f, 0.f, 0.f);
        if (row < n_rows) {
            int g = row_off + row;
            int deg = g_cnt[g];
            if (deg > CAP) deg = CAP;
            const int* bk = g_bucket + (size_t)g * CAP;
            for (int j = 0; j < deg; j++) {
                int s = bk[j];
                float rs = rsqrtf(fmaxf((float)g_outdeg[rel * MAXN + s], 1.f));
                float4 v = ((const float4*)(X + (size_t)s * D))[lane];
                acc.x = fmaf(v.x, rs, acc.x);
                acc.y = fmaf(v.y, rs, acc.y);
                acc.z = fmaf(v.z, rs, acc.z);
                acc.w = fmaf(v.w, rs, acc.w);
            }
        }
        ((float4*)(sA + r * SAS))[lane] = acc;
    }
    __syncthreads();

    // ---- GEMM phase: 16x16 thread grid; each thread 4 rows x 8 cols ----
    const int ty = tid >> 4;        // row group 0..15
    const int tx = tid & 15;        // col group 0..15
    const int r4 = ty * 4;
    float acc[4][8];
#pragma unroll
    for (int i = 0; i < 4; i++)
#pragma unroll
        for (int j = 0; j < 8; j++) acc[i][j] = 0.f;

#pragma unroll 4
    for (int k = 0; k < D; k++) {
        float a0 = sA[(r4 + 0) * SAS + k];
        float a1 = sA[(r4 + 1) * SAS + k];
        float a2 = sA[(r4 + 2) * SAS + k];
        float a3 = sA[(r4 + 3) * SAS + k];
        float4 b0 = *(const float4*)(sW + k * D + tx * 4);
        float4 b1 = *(const float4*)(sW + k * D + 64 + tx * 4);
        acc[0][0] = fmaf(a0, b0.x, acc[0][0]); acc[0][1] = fmaf(a0, b0.y, acc[0][1]);
        acc[0][2] = fmaf(a0, b0.z, acc[0][2]); acc[0][3] = fmaf(a0, b0.w, acc[0][3]);
        acc[0][4] = fmaf(a0, b1.x, acc[0][4]); acc[0][5] = fmaf(a0, b1.y, acc[0][5]);
        acc[0][6] = fmaf(a0, b1.z, acc[0][6]); acc[0][7] = fmaf(a0, b1.w, acc[0][7]);
        acc[1][0] = fmaf(a1, b0.x, acc[1][0]); acc[1][1] = fmaf(a1, b0.y, acc[1][1]);
        acc[1][2] = fmaf(a1, b0.z, acc[1][2]); acc[1][3] = fmaf(a1, b0.w, acc[1][3]);
        acc[1][4] = fmaf(a1, b1.x, acc[1][4]); acc[1][5] = fmaf(a1, b1.y, acc[1][5]);
        acc[1][6] = fmaf(a1, b1.z, acc[1][6]); acc[1][7] = fmaf(a1, b1.w, acc[1][7]);
        acc[2][0] = fmaf(a2, b0.x, acc[2][0]); acc[2][1] = fmaf(a2, b0.y, acc[2][1]);
        acc[2][2] = fmaf(a2, b0.z, acc[2][2]); acc[2][3] = fmaf(a2, b0.w, acc[2][3]);
        acc[2][4] = fmaf(a2, b1.x, acc[2][4]); acc[2][5] = fmaf(a2, b1.y, acc[2][5]);
        acc[2][6] = fmaf(a2, b1.z, acc[2][6]); acc[2][7] = fmaf(a2, b1.w, acc[2][7]);
        acc[3][0] = fmaf(a3, b0.x, acc[3][0]); acc[3][1] = fmaf(a3, b0.y, acc[3][1]);
        acc[3][2] = fmaf(a3, b0.z, acc[3][2]); acc[3][3] = fmaf(a3, b0.w, acc[3][3]);
        acc[3][4] = fmaf(a3, b1.x, acc[3][4]); acc[3][5] = fmaf(a3, b1.y, acc[3][5]);
        acc[3][6] = fmaf(a3, b1.z, acc[3][6]); acc[3][7] = fmaf(a3, b1.w, acc[3][7]);
    }

    // ---- Epilogue ----
    float4 bv0 = *(const float4*)(bias + tx * 4);
    float4 bv1 = *(const float4*)(bias + 64 + tx * 4);
#pragma unroll
    for (int i = 0; i < 4; i++) {
        int row = row0 + r4 + i;
        if (row >= n_rows) continue;
        float rs = rsqrtf(fmaxf((float)g_cnt[row_off + row], 1.f));
        float4 v0, v1;
        v0.x = (acc[i][0] * rs + bv0.x) * scale;
        v0.y = (acc[i][1] * rs + bv0.y) * scale;
        v0.z = (acc[i][2] * rs + bv0.z) * scale;
        v0.w = (acc[i][3] * rs + bv0.w) * scale;
        v1.x = (acc[i][4] * rs + bv1.x) * scale;
        v1.y = (acc[i][5] * rs + bv1.y) * scale;
        v1.z = (acc[i][6] * rs + bv1.z) * scale;
        v1.w = (acc[i][7] * rs + bv1.w) * scale;
        float* o0 = out + (size_t)row * D + tx * 4;
        float* o1 = o0 + 64;
        if (!(flags & 1)) {
            float4 p0 = *(const float4*)o0;
            float4 p1 = *(const float4*)o1;
            v0.x += p0.x; v0.y += p0.y; v0.z += p0.z; v0.w += p0.w;
            v1.x += p1.x; v1.y += p1.y; v1.z += p1.z; v1.w += p1.w;
        }
        if (flags & 2) {
            v0.x = fmaxf(v0.x, 0.f); v0.y = fmaxf(v0.y, 0.f);
            v0.z = fmaxf(v0.z, 0.f); v0.w = fmaxf(v0.w, 0.f);
            v1.x = fmaxf(v1.x, 0.f); v1.y = fmaxf(v1.y, 0.f);
            v1.z = fmaxf(v1.z, 0.f); v1.w = fmaxf(v1.w, 0.f);
        }
        *(float4*)o0 = v0;
        *(float4*)o1 = v1;
    }
}

// ---------------------------------------------------------------------------
extern "C" void kernel_launch(void* const* d_in, const int* in_sizes, int n_in,
                              void* d_out, int out_size) {
    const float* node_feat = (const float*)d_in[0];
    const float* inst_feat = (const float*)d_in[1];
    const float* svc_feat  = (const float*)d_in[2];

    const int*   e_src[NREL];
    const int*   e_dst[NREL];
    const float* W[NREL];
    const float* B[NREL];
    for (int r = 0; r < NREL; r++) {
        e_src[r] = (const int*)  d_in[3 + r * 4 + 0];
        e_dst[r] = (const int*)  d_in[3 + r * 4 + 1];
        W[r]     = (const float*)d_in[3 + r * 4 + 2];
        B[r]     = (const float*)d_in[3 + r * 4 + 3];
    }

    // Relation order: sc, in, ni, ii, si, is
    const float* srcfeat[NREL] = { svc_feat, inst_feat, node_feat, inst_feat, svc_feat, inst_feat };
    const int row_off[NREL] = { 0, 20000, 30000, 80000, 130000, 180000 };

    float* out = (float*)d_out;
    float* out_inst = out + (size_t)N_NODE * D;
    float* out_svc  = out + (size_t)(N_NODE + N_INST) * D;

    const size_t smem = (size_t)(D * D + TILE * SAS) * sizeof(float);  // ~97 KB
    static bool attr_set = false;
    if (!attr_set) {
        cudaFuncSetAttribute(gconv_fused_kernel,
                             cudaFuncAttributeMaxDynamicSharedMemorySize, (int)smem);
        attr_set = true;
    }

    // 1. zero counts
    zero_counts_kernel<<<512, 256>>>();

    // 2. build buckets + out-degrees (all relations, one launch)
    build_kernel<<<(NREL * NEDGE + 255) / 256, 256>>>(
        e_src[0], e_dst[0], e_src[1], e_dst[1], e_src[2], e_dst[2],
        e_src[3], e_dst[3], e_src[4], e_dst[4], e_src[5], e_dst[5]);

    // 3. fused gconv per relation
    // node (10000 rows): rel 'in'(1), overwrite + relu
    gconv_fused_kernel<<<(N_NODE + TILE - 1) / TILE, 256, smem>>>(
        srcfeat[1], W[1], B[1], out, 1, row_off[1], N_NODE, 1.0f, 3);

    // instance (50000 rows): mean of ni(2), ii(3), si(4)
    const int ib = (N_INST + TILE - 1) / TILE;
    gconv_fused_kernel<<<ib, 256, smem>>>(srcfeat[2], W[2], B[2], out_inst,
                                          2, row_off[2], N_INST, 1.0f / 3.0f, 1);
    gconv_fused_kernel<<<ib, 256, smem>>>(srcfeat[3], W[3], B[3], out_inst,
                                          3, row_off[3], N_INST, 1.0f / 3.0f, 0);
    gconv_fused_kernel<<<ib, 256, smem>>>(srcfeat[4], W[4], B[4], out_inst,
                                          4, row_off[4], N_INST, 1.0f / 3.0f, 2);

    // svc (20000 rows): mean of sc(0), is(5)
    const int sb = (N_SVC + TILE - 1) / TILE;
    gconv_fused_kernel<<<sb, 256, smem>>>(srcfeat[0], W[0], B[0], out_svc,
                                          0, row_off[0], N_SVC, 0.5f, 1);
    gconv_fused_kernel<<<sb, 256, smem>>>(srcfeat[5], W[5], B[5], out_svc,
                                          5, row_off[5], N_SVC, 0.5f, 2);
}

// round 6
// speedup vs baseline: 1.9060x; 1.2192x over previous
#include <cuda_runtime.h>
#include <cstddef>

#define N_NODE 10000
#define N_INST 50000
#define N_SVC  20000
#define NEDGE  200000
#define D      128
#define NREL   6
#define MAXN   50000
#define TOTAL_DST_ROWS 200000
#define CAP 128            // bucket capacity per dst row
#define TILE 64            // rows per GEMM block
#define SAS 132            // sA row stride (floats)

// Static scratch.
__device__ int   g_bucket[(size_t)TOTAL_DST_ROWS * CAP];  // ~102.4 MB
__device__ int   g_cnt[TOTAL_DST_ROWS];
__device__ int   g_outdeg[NREL * MAXN];
__device__ float g_agg[(size_t)TOTAL_DST_ROWS * D];       // ~102.4 MB (pre-scaled)

// ---------------------------------------------------------------------------
__global__ void zero_counts_kernel() {
    int i = blockIdx.x * blockDim.x + threadIdx.x;
    int stride = gridDim.x * blockDim.x;
    for (int j = i; j < TOTAL_DST_ROWS; j += stride) g_cnt[j] = 0;
    for (int j = i; j < NREL * MAXN; j += stride) g_outdeg[j] = 0;
}

// ---------------------------------------------------------------------------
// One pass over all 6 relations: out-degree histogram + bucket fill.
__global__ void build_kernel(const int* __restrict__ s0, const int* __restrict__ d0,
                             const int* __restrict__ s1, const int* __restrict__ d1,
                             const int* __restrict__ s2, const int* __restrict__ d2,
                             const int* __restrict__ s3, const int* __restrict__ d3,
                             const int* __restrict__ s4, const int* __restrict__ d4,
                             const int* __restrict__ s5, const int* __restrict__ d5) {
    int i = blockIdx.x * blockDim.x + threadIdx.x;
    if (i >= NREL * NEDGE) return;
    int rel = i / NEDGE;
    int e = i - rel * NEDGE;
    const int* sp; const int* dp; int off;
    switch (rel) {
        case 0: sp = s0; dp = d0; off = 0;      break;  // sc -> svc rows
        case 1: sp = s1; dp = d1; off = 20000;  break;  // in -> node rows
        case 2: sp = s2; dp = d2; off = 30000;  break;  // ni -> inst rows
        case 3: sp = s3; dp = d3; off = 80000;  break;  // ii -> inst rows
        case 4: sp = s4; dp = d4; off = 130000; break;  // si -> inst rows
        default: sp = s5; dp = d5; off = 180000; break; // is -> svc rows
    }
    int s = sp[e];
    int d = dp[e];
    atomicAdd(&g_outdeg[rel * MAXN + s], 1);
    int pos = atomicAdd(&g_cnt[off + d], 1);
    if (pos < CAP) g_bucket[(size_t)(off + d) * CAP + pos] = s;
}

// ---------------------------------------------------------------------------
// Gather: warp per dst row across ALL relations. No smem -> max occupancy.
//   g_agg[row] = scale * rsqrt(max(indeg,1)) *
//                sum_{e in bucket(row)} X_rel[src_e] * rsqrt(max(outdeg_rel[src_e],1))
__global__ void gather_all_kernel(const float* __restrict__ X0,  // svc  (sc)
                                  const float* __restrict__ X1,  // inst (in)
                                  const float* __restrict__ X2,  // node (ni)
                                  const float* __restrict__ X3,  // inst (ii)
                                  const float* __restrict__ X4,  // svc  (si)
                                  const float* __restrict__ X5)  // inst (is)
{
    int gw = (blockIdx.x * blockDim.x + threadIdx.x) >> 5;
    int lane = threadIdx.x & 31;
    if (gw >= TOTAL_DST_ROWS) return;

    int rel; const float* X; float scale;
    if      (gw < 20000)  { rel = 0; X = X0; scale = 0.5f; }
    else if (gw < 30000)  { rel = 1; X = X1; scale = 1.0f; }
    else if (gw < 80000)  { rel = 2; X = X2; scale = 1.0f / 3.0f; }
    else if (gw < 130000) { rel = 3; X = X3; scale = 1.0f / 3.0f; }
    else if (gw < 180000) { rel = 4; X = X4; scale = 1.0f / 3.0f; }
    else                  { rel = 5; X = X5; scale = 0.5f; }

    int cnt = g_cnt[gw];
    int deg = cnt < CAP ? cnt : CAP;
    const int* bk = g_bucket + (size_t)gw * CAP;
    const int* od = g_outdeg + rel * MAXN;
    const float4* X4p = (const float4*)X;

    float4 acc = make_float4(0.f, 0.f, 0.f, 0.f);
    for (int j = 0; j < deg; j++) {
        int s = bk[j];
        float rs = rsqrtf(fmaxf((float)od[s], 1.f));
        float4 v = X4p[(size_t)s * 32 + lane];
        acc.x = fmaf(v.x, rs, acc.x);
        acc.y = fmaf(v.y, rs, acc.y);
        acc.z = fmaf(v.z, rs, acc.z);
        acc.w = fmaf(v.w, rs, acc.w);
    }
    float c = rsqrtf(fmaxf((float)cnt, 1.f)) * scale;
    acc.x *= c; acc.y *= c; acc.z *= c; acc.w *= c;
    ((float4*)g_agg)[(size_t)gw * 32 + lane] = acc;
}

// ---------------------------------------------------------------------------
// Concatenated-K GEMM: out[row] = relu( sum_r A_r[row] @ W_r + scale*sum_r b_r )
// A_r rows are pre-scaled by the gather. 256 threads, 64 rows x 128 cols/block,
// 4x8 register tile/thread. K chunks of 128 (one per relation).
__global__ void gemm_multi_kernel(int nrel,
                                  int offA0, int offA1, int offA2,
                                  const float* __restrict__ W0,
                                  const float* __restrict__ W1,
                                  const float* __restrict__ W2,
                                  const float* __restrict__ b0,
                                  const float* __restrict__ b1,
                                  const float* __restrict__ b2,
                                  float* __restrict__ out,
                                  int n_rows, float scale) {
    extern __shared__ float sh[];
    float* sW = sh;             // [128*128]
    float* sA = sh + D * D;     // [TILE * SAS]

    const int tid = threadIdx.x;
    const int row0 = blockIdx.x * TILE;
    const int ty = tid >> 4;    // 0..15
    const int tx = tid & 15;    // 0..15
    const int r4 = ty * 4;

    float acc[4][8];
#pragma unroll
    for (int i = 0; i < 4; i++)
#pragma unroll
        for (int j = 0; j < 8; j++) acc[i][j] = 0.f;

    for (int r = 0; r < nrel; r++) {
        const float* W = (r == 0) ? W0 : (r == 1) ? W1 : W2;
        int offA = (r == 0) ? offA0 : (r == 1) ? offA1 : offA2;
        const float* A = g_agg + (size_t)offA * D;

        // Stage W chunk (16384 floats = 4096 float4).
        {
            const float4* Wv = (const float4*)W;
            float4* sWv = (float4*)sW;
#pragma unroll
            for (int i = 0; i < 16; i++) sWv[tid + i * 256] = Wv[tid + i * 256];
        }
        // Stage A tile (64 rows x 128) -> sA, coalesced.
        {
            const float4 z = make_float4(0.f, 0.f, 0.f, 0.f);
#pragma unroll
            for (int i = 0; i < 8; i++) {
                int idx = tid + i * 256;        // float4 index, 0..2047
                int row = idx >> 5;
                int k4 = idx & 31;
                float4 v = (row0 + row < n_rows)
                         ? ((const float4*)(A + (size_t)(row0 + row) * D))[k4] : z;
                *(float4*)(sA + row * SAS + k4 * 4) = v;
            }
        }
        __syncthreads();

#pragma unroll 4
        for (int k = 0; k < D; k++) {
            float a0 = sA[(r4 + 0) * SAS + k];
            float a1 = sA[(r4 + 1) * SAS + k];
            float a2 = sA[(r4 + 2) * SAS + k];
            float a3 = sA[(r4 + 3) * SAS + k];
            float4 c0 = *(const float4*)(sW + k * D + tx * 4);
            float4 c1 = *(const float4*)(sW + k * D + 64 + tx * 4);
            acc[0][0] = fmaf(a0, c0.x, acc[0][0]); acc[0][1] = fmaf(a0, c0.y, acc[0][1]);
            acc[0][2] = fmaf(a0, c0.z, acc[0][2]); acc[0][3] = fmaf(a0, c0.w, acc[0][3]);
            acc[0][4] = fmaf(a0, c1.x, acc[0][4]); acc[0][5] = fmaf(a0, c1.y, acc[0][5]);
            acc[0][6] = fmaf(a0, c1.z, acc[0][6]); acc[0][7] = fmaf(a0, c1.w, acc[0][7]);
            acc[1][0] = fmaf(a1, c0.x, acc[1][0]); acc[1][1] = fmaf(a1, c0.y, acc[1][1]);
            acc[1][2] = fmaf(a1, c0.z, acc[1][2]); acc[1][3] = fmaf(a1, c0.w, acc[1][3]);
            acc[1][4] = fmaf(a1, c1.x, acc[1][4]); acc[1][5] = fmaf(a1, c1.y, acc[1][5]);
            acc[1][6] = fmaf(a1, c1.z, acc[1][6]); acc[1][7] = fmaf(a1, c1.w, acc[1][7]);
            acc[2][0] = fmaf(a2, c0.x, acc[2][0]); acc[2][1] = fmaf(a2, c0.y, acc[2][1]);
            acc[2][2] = fmaf(a2, c0.z, acc[2][2]); acc[2][3] = fmaf(a2, c0.w, acc[2][3]);
            acc[2][4] = fmaf(a2, c1.x, acc[2][4]); acc[2][5] = fmaf(a2, c1.y, acc[2][5]);
            acc[2][6] = fmaf(a2, c1.z, acc[2][6]); acc[2][7] = fmaf(a2, c1.w, acc[2][7]);
            acc[3][0] = fmaf(a3, c0.x, acc[3][0]); acc[3][1] = fmaf(a3, c0.y, acc[3][1]);
            acc[3][2] = fmaf(a3, c0.z, acc[3][2]); acc[3][3] = fmaf(a3, c0.w, acc[3][3]);
            acc[3][4] = fmaf(a3, c1.x, acc[3][4]); acc[3][5] = fmaf(a3, c1.y, acc[3][5]);
            acc[3][6] = fmaf(a3, c1.z, acc[3][6]); acc[3][7] = fmaf(a3, c1.w, acc[3][7]);
        }
        __syncthreads();
    }

    // Epilogue: combined bias (scaled) + relu, single write.
    float bs0[4], bs1[4];
#pragma unroll
    for (int j = 0; j < 4; j++) {
        float v0 = b0[tx * 4 + j], v1 = b0[64 + tx * 4 + j];
        if (nrel > 1) { v0 += b1[tx * 4 + j]; v1 += b1[64 + tx * 4 + j]; }
        if (nrel > 2) { v0 += b2[tx * 4 + j]; v1 += b2[64 + tx * 4 + j]; }
        bs0[j] = v0 * scale;
        bs1[j] = v1 * scale;
    }
#pragma unroll
    for (int i = 0; i < 4; i++) {
        int row = row0 + r4 + i;
        if (row >= n_rows) continue;
        float4 v0, v1;
        v0.x = fmaxf(acc[i][0] + bs0[0], 0.f);
        v0.y = fmaxf(acc[i][1] + bs0[1], 0.f);
        v0.z = fmaxf(acc[i][2] + bs0[2], 0.f);
        v0.w = fmaxf(acc[i][3] + bs0[3], 0.f);
        v1.x = fmaxf(acc[i][4] + bs1[0], 0.f);
        v1.y = fmaxf(acc[i][5] + bs1[1], 0.f);
        v1.z = fmaxf(acc[i][6] + bs1[2], 0.f);
        v1.w = fmaxf(acc[i][7] + bs1[3], 0.f);
        *(float4*)(out + (size_t)row * D + tx * 4) = v0;
        *(float4*)(out + (size_t)row * D + 64 + tx * 4) = v1;
    }
}

// ---------------------------------------------------------------------------
extern "C" void kernel_launch(void* const* d_in, const int* in_sizes, int n_in,
                              void* d_out, int out_size) {
    const float* node_feat = (const float*)d_in[0];
    const float* inst_feat = (const float*)d_in[1];
    const float* svc_feat  = (const float*)d_in[2];

    const int*   e_src[NREL];
    const int*   e_dst[NREL];
    const float* W[NREL];
    const float* B[NREL];
    for (int r = 0; r < NREL; r++) {
        e_src[r] = (const int*)  d_in[3 + r * 4 + 0];
        e_dst[r] = (const int*)  d_in[3 + r * 4 + 1];
        W[r]     = (const float*)d_in[3 + r * 4 + 2];
        B[r]     = (const float*)d_in[3 + r * 4 + 3];
    }

    float* out = (float*)d_out;
    float* out_inst = out + (size_t)N_NODE * D;
    float* out_svc  = out + (size_t)(N_NODE + N_INST) * D;

    const size_t smem = (size_t)(D * D + TILE * SAS) * sizeof(float);  // ~97.5 KB
    static bool attr_set = false;
    if (!attr_set) {
        cudaFuncSetAttribute(gemm_multi_kernel,
                             cudaFuncAttributeMaxDynamicSharedMemorySize, (int)smem);
        attr_set = true;
    }

    // 1. zero counts
    zero_counts_kernel<<<512, 256>>>();

    // 2. build buckets + out-degrees
    build_kernel<<<(NREL * NEDGE + 255) / 256, 256>>>(
        e_src[0], e_dst[0], e_src[1], e_dst[1], e_src[2], e_dst[2],
        e_src[3], e_dst[3], e_src[4], e_dst[4], e_src[5], e_dst[5]);

    // 3. gather all relations, fold rsqrt(indeg)*scale into rows
    gather_all_kernel<<<(TOTAL_DST_ROWS * 32 + 255) / 256, 256>>>(
        svc_feat, inst_feat, node_feat, inst_feat, svc_feat, inst_feat);

    // 4. one concat-K GEMM per destination type
    // node: rel in (agg rows 20000..29999), K=128
    gemm_multi_kernel<<<(N_NODE + TILE - 1) / TILE, 256, smem>>>(
        1, 20000, 0, 0, W[1], 0, 0, B[1], 0, 0, out, N_NODE, 1.0f);
    // inst: rels ni(30000), ii(80000), si(130000), K=384
    gemm_multi_kernel<<<(N_INST + TILE - 1) / TILE, 256, smem>>>(
        3, 30000, 80000, 130000, W[2], W[3], W[4], B[2], B[3], B[4],
        out_inst, N_INST, 1.0f / 3.0f);
    // svc: rels sc(0), is(180000), K=256
    gemm_multi_kernel<<<(N_SVC + TILE - 1) / TILE, 256, smem>>>(
        2, 0, 180000, 0, W[0], W[5], 0, B[0], B[5], 0,
        out_svc, N_SVC, 0.5f);
}

// round 11
// speedup vs baseline: 2.7715x; 1.4541x over previous
#include <cuda_runtime.h>
#include <cuda_bf16.h>
#include <cstddef>
#include <cstdint>

#define N_NODE 10000
#define N_INST 50000
#define N_SVC  20000
#define NEDGE  200000
#define D      128
#define NREL   6
#define MAXN   50000
#define TOTAL_DST_ROWS 200000
#define CAP 128
#define TILE_ELEMS 16384         // 128x128 bf16 elements per tile (32 KB)
#define NTILE 1566               // sc:157 in:79 ni:391 ii:391 si:391 is:157
// Tile bases: sc=0, in=157, ni=236, ii=627, si=1018, is=1409

// Static scratch.
__device__ int   g_bucket[(size_t)TOTAL_DST_ROWS * CAP];   // ~102 MB
__device__ int   g_cnt[TOTAL_DST_ROWS];
__device__ int   g_outdeg[NREL * MAXN];
__device__ __nv_bfloat16 g_Ahi[(size_t)NTILE * TILE_ELEMS]; // 51.3 MB
__device__ __nv_bfloat16 g_Alo[(size_t)NTILE * TILE_ELEMS]; // 51.3 MB
__device__ __nv_bfloat16 g_Bhi[NREL * TILE_ELEMS];
__device__ __nv_bfloat16 g_Blo[NREL * TILE_ELEMS];

// ---------------------------------------------------------------------------
__device__ __forceinline__ uint32_t smem_u32(const void* p) {
    uint32_t a;
    asm("{ .reg .u64 t; cvta.to.shared.u64 t, %1; cvt.u32.u64 %0, t; }"
        : "=r"(a) : "l"(p));
    return a;
}

// ldmatrix XOR swizzle: 256 B/row; 16B chunk id XORed with (row&7) in low 3 bits.
__device__ __forceinline__ uint32_t swz_off(int r, int chunk) {
    return (uint32_t)(r * 256 + (((chunk & 8) | ((chunk ^ (r & 7)) & 7)) << 4));
}

#define LDSM_X4(r0, r1, r2, r3, addr) \
    asm volatile("ldmatrix.sync.aligned.m8n8.x4.shared.b16 {%0,%1,%2,%3}, [%4];" \
                 : "=r"(r0), "=r"(r1), "=r"(r2), "=r"(r3) : "r"(addr))

__device__ __forceinline__ void mma16816(float* c, const uint32_t* a, const uint32_t* b) {
    asm volatile("mma.sync.aligned.m16n8k16.row.col.f32.bf16.bf16.f32 "
                 "{%0,%1,%2,%3}, {%4,%5,%6,%7}, {%8,%9}, {%0,%1,%2,%3};"
                 : "+f"(c[0]), "+f"(c[1]), "+f"(c[2]), "+f"(c[3])
                 : "r"(a[0]), "r"(a[1]), "r"(a[2]), "r"(a[3]),
                   "r"(b[0]), "r"(b[1]));
}

// ---------------------------------------------------------------------------
__global__ void zero_counts_kernel() {
    int i = blockIdx.x * blockDim.x + threadIdx.x;
    int stride = gridDim.x * blockDim.x;
    for (int j = i; j < TOTAL_DST_ROWS; j += stride) g_cnt[j] = 0;
    for (int j = i; j < NREL * MAXN; j += stride) g_outdeg[j] = 0;
}

// ---------------------------------------------------------------------------
__global__ void build_kernel(const int* __restrict__ s0, const int* __restrict__ d0,
                             const int* __restrict__ s1, const int* __restrict__ d1,
                             const int* __restrict__ s2, const int* __restrict__ d2,
                             const int* __restrict__ s3, const int* __restrict__ d3,
                             const int* __restrict__ s4, const int* __restrict__ d4,
                             const int* __restrict__ s5, const int* __restrict__ d5) {
    int i = blockIdx.x * blockDim.x + threadIdx.x;
    if (i >= NREL * NEDGE) return;
    int rel = i / NEDGE;
    int e = i - rel * NEDGE;
    const int* sp; const int* dp; int off;
    switch (rel) {
        case 0: sp = s0; dp = d0; off = 0;      break;
        case 1: sp = s1; dp = d1; off = 20000;  break;
        case 2: sp = s2; dp = d2; off = 30000;  break;
        case 3: sp = s3; dp = d3; off = 80000;  break;
        case 4: sp = s4; dp = d4; off = 130000; break;
        default: sp = s5; dp = d5; off = 180000; break;
    }
    int s = sp[e];
    int d = dp[e];
    atomicAdd(&g_outdeg[rel * MAXN + s], 1);
    int pos = atomicAdd(&g_cnt[off + d], 1);
    if (pos < CAP) g_bucket[(size_t)(off + d) * CAP + pos] = s;
}

// ---------------------------------------------------------------------------
// Pre-split W into K-major (B[n][k]) swizzled bf16 tiles.
__global__ void prep_w_kernel(const float* __restrict__ W0, const float* __restrict__ W1,
                              const float* __restrict__ W2, const float* __restrict__ W3,
                              const float* __restrict__ W4, const float* __restrict__ W5) {
    int rel = blockIdx.x;
    const float* W;
    switch (rel) {
        case 0: W = W0; break; case 1: W = W1; break; case 2: W = W2; break;
        case 3: W = W3; break; case 4: W = W4; break; default: W = W5; break;
    }
    char* bh = (char*)(g_Bhi + (size_t)rel * TILE_ELEMS);
    char* bl = (char*)(g_Blo + (size_t)rel * TILE_ELEMS);
    for (int idx = threadIdx.x; idx < D * D; idx += blockDim.x) {
        int k = idx >> 7, n = idx & 127;       // W[k][n] -> B[n][k]
        float v = W[idx];
        __nv_bfloat16 h = __float2bfloat16(v);
        __nv_bfloat16 l = __float2bfloat16(v - __bfloat162float(h));
        uint32_t p = swz_off(n, k >> 3) + (uint32_t)((k & 7) * 2);
        *(__nv_bfloat16*)(bh + p) = h;
        *(__nv_bfloat16*)(bl + p) = l;
    }
}

// ---------------------------------------------------------------------------
// Gather: warp per padded dst row; writes split-bf16 into swizzled tiles.
__global__ void gather_all_kernel(const float* __restrict__ X0,  // svc  (sc)
                                  const float* __restrict__ X1,  // inst (in)
                                  const float* __restrict__ X2,  // node (ni)
                                  const float* __restrict__ X3,  // inst (ii)
                                  const float* __restrict__ X4,  // svc  (si)
                                  const float* __restrict__ X5)  // inst (is)
{
    int gw = (blockIdx.x * blockDim.x + threadIdx.x) >> 5;   // padded row id
    int lane = threadIdx.x & 31;
    int tile = gw >> 7;
    if (tile >= NTILE) return;

    int rel, pbase, segN, tbase; const float* X; float scale;
    if      (tile < 157)  { rel = 0; X = X0; scale = 0.5f;      pbase = 0;      segN = 20000; tbase = 0; }
    else if (tile < 236)  { rel = 1; X = X1; scale = 1.0f;      pbase = 20000;  segN = 10000; tbase = 157; }
    else if (tile < 627)  { rel = 2; X = X2; scale = 1.f / 3.f; pbase = 30000;  segN = 50000; tbase = 236; }
    else if (tile < 1018) { rel = 3; X = X3; scale = 1.f / 3.f; pbase = 80000;  segN = 50000; tbase = 627; }
    else if (tile < 1409) { rel = 4; X = X4; scale = 1.f / 3.f; pbase = 130000; segN = 50000; tbase = 1018; }
    else                  { rel = 5; X = X5; scale = 0.5f;      pbase = 180000; segN = 20000; tbase = 1409; }

    int local = gw - (tbase << 7);
    float4 acc = make_float4(0.f, 0.f, 0.f, 0.f);
    if (local < segN) {
        int g = pbase + local;
        int cnt = g_cnt[g];
        int deg = cnt < CAP ? cnt : CAP;
        const int* bk = g_bucket + (size_t)g * CAP;
        const int* od = g_outdeg + rel * MAXN;
        const float4* Xv = (const float4*)X;
        for (int j = 0; j < deg; j++) {
            int s = bk[j];
            float rs = rsqrtf(fmaxf((float)od[s], 1.f));
            float4 v = Xv[(size_t)s * 32 + lane];
            acc.x = fmaf(v.x, rs, acc.x);
            acc.y = fmaf(v.y, rs, acc.y);
            acc.z = fmaf(v.z, rs, acc.z);
            acc.w = fmaf(v.w, rs, acc.w);
        }
        float c = rsqrtf(fmaxf((float)cnt, 1.f)) * scale;
        acc.x *= c; acc.y *= c; acc.z *= c; acc.w *= c;
    }
    __nv_bfloat16 h0 = __float2bfloat16(acc.x);
    __nv_bfloat16 h1 = __float2bfloat16(acc.y);
    __nv_bfloat16 h2 = __float2bfloat16(acc.z);
    __nv_bfloat16 h3 = __float2bfloat16(acc.w);
    __nv_bfloat16 l0 = __float2bfloat16(acc.x - __bfloat162float(h0));
    __nv_bfloat16 l1 = __float2bfloat16(acc.y - __bfloat162float(h1));
    __nv_bfloat16 l2 = __float2bfloat16(acc.z - __bfloat162float(h2));
    __nv_bfloat16 l3 = __float2bfloat16(acc.w - __bfloat162float(h3));

    int r = gw & 127;
    // lane covers 8 bytes: chunk = lane>>1, inner 8B = (lane&1)*8
    uint32_t p = swz_off(r, lane >> 1) + (uint32_t)((lane & 1) * 8);
    char* bh = (char*)g_Ahi + (size_t)tile * TILE_ELEMS * 2 + p;
    char* bl = (char*)g_Alo + (size_t)tile * TILE_ELEMS * 2 + p;
    union { __nv_bfloat162 b2[2]; uint2 u; } uh, ul;
    uh.b2[0] = __halves2bfloat162(h0, h1); uh.b2[1] = __halves2bfloat162(h2, h3);
    ul.b2[0] = __halves2bfloat162(l0, l1); ul.b2[1] = __halves2bfloat162(l2, l3);
    *(uint2*)bh = uh.u;
    *(uint2*)bl = ul.u;
}

// ---------------------------------------------------------------------------
// HMMA GEMM: 128x128 output per block, 8 warps (4x2), mma.m16n8k16 bf16.
// 3 split products per relation chunk, fp32 register accumulators.
#define OFF_AHI 0
#define OFF_ALO 32768
#define OFF_BHI 65536
#define OFF_BLO 98304
#define SMEM_BYTES 131072

// One K=128 pass: acc += A(sA) @ B(sB)^T using the swizzled smem tiles.
__device__ __forceinline__ void mma_pass(uint32_t sA, uint32_t sB,
                                         float acc[2][8][4], int lane,
                                         int wm, int wn) {
#pragma unroll
    for (int ks = 0; ks < 8; ks++) {
        uint32_t a[2][4];
#pragma unroll
        for (int mt = 0; mt < 2; mt++) {
            int row = wm * 32 + mt * 16 + (lane & 15);
            int chunk = ks * 2 + (lane >> 4);
            LDSM_X4(a[mt][0], a[mt][1], a[mt][2], a[mt][3], sA + swz_off(row, chunk));
        }
        uint32_t b[8][2];
#pragma unroll
        for (int jp = 0; jp < 4; jp++) {     // ntile pair (2jp, 2jp+1)
            int quarter = lane >> 3;
            int nrow = wn * 64 + (jp * 2 + (quarter >> 1)) * 8 + (lane & 7);
            int chunk = ks * 2 + (quarter & 1);
            LDSM_X4(b[jp * 2][0], b[jp * 2][1], b[jp * 2 + 1][0], b[jp * 2 + 1][1],
                    sB + swz_off(nrow, chunk));
        }
#pragma unroll
        for (int mt = 0; mt < 2; mt++)
#pragma unroll
            for (int nt = 0; nt < 8; nt++)
                mma16816(acc[mt][nt], a[mt], b[nt]);
    }
}

__global__ void __launch_bounds__(256, 1)
tc_gemm_kernel(const float* __restrict__ b_sc, const float* __restrict__ b_in,
               const float* __restrict__ b_ni, const float* __restrict__ b_ii,
               const float* __restrict__ b_si, const float* __restrict__ b_is,
               float* __restrict__ out) {
    extern __shared__ char smem[];
    uint32_t sb = smem_u32(smem);
    int tid = threadIdx.x, wid = tid >> 5, lane = tid & 31;
    int wm = wid >> 1, wn = wid & 1;
    int b = blockIdx.x;

    int nrel, bl, n_rows;
    int tiles[3]; int rels[3];
    const float* bias0; const float* bias1; const float* bias2;
    float scale; float* obase;
    if (b < 79) {
        bl = b; nrel = 1; n_rows = N_NODE; scale = 1.0f; obase = out;
        tiles[0] = 157 + bl; rels[0] = 1;
        bias0 = b_in; bias1 = 0; bias2 = 0;
    } else if (b < 470) {
        bl = b - 79; nrel = 3; n_rows = N_INST; scale = 1.f / 3.f;
        obase = out + (size_t)N_NODE * D;
        tiles[0] = 236 + bl; tiles[1] = 627 + bl; tiles[2] = 1018 + bl;
        rels[0] = 2; rels[1] = 3; rels[2] = 4;
        bias0 = b_ni; bias1 = b_ii; bias2 = b_si;
    } else {
        bl = b - 470; nrel = 2; n_rows = N_SVC; scale = 0.5f;
        obase = out + (size_t)(N_NODE + N_INST) * D;
        tiles[0] = bl; tiles[1] = 1409 + bl;
        rels[0] = 0; rels[1] = 5;
        bias0 = b_sc; bias1 = b_is; bias2 = 0;
    }
    int row0 = bl * 128;

    float acc[2][8][4];
#pragma unroll
    for (int i = 0; i < 2; i++)
#pragma unroll
        for (int j = 0; j < 8; j++)
#pragma unroll
            for (int k = 0; k < 4; k++) acc[i][j][k] = 0.f;

    for (int r = 0; r < nrel; r++) {
        if (r > 0) __syncthreads();   // previous compute done before overwrite
        // Linear stage of pre-swizzled tiles (2048 uint4 each).
        const uint4* sAh = (const uint4*)(g_Ahi + (size_t)tiles[r] * TILE_ELEMS);
        const uint4* sAl = (const uint4*)(g_Alo + (size_t)tiles[r] * TILE_ELEMS);
        const uint4* sBh = (const uint4*)(g_Bhi + (size_t)rels[r] * TILE_ELEMS);
        const uint4* sBl = (const uint4*)(g_Blo + (size_t)rels[r] * TILE_ELEMS);
        uint4* dAh = (uint4*)(smem + OFF_AHI);
        uint4* dAl = (uint4*)(smem + OFF_ALO);
        uint4* dBh = (uint4*)(smem + OFF_BHI);
        uint4* dBl = (uint4*)(smem + OFF_BLO);
#pragma unroll
        for (int i = 0; i < 8; i++) {
            int idx = tid + i * 256;
            dAh[idx] = sAh[idx];
            dAl[idx] = sAl[idx];
            dBh[idx] = sBh[idx];
            dBl[idx] = sBl[idx];
        }
        __syncthreads();

        mma_pass(sb + OFF_AHI, sb + OFF_BHI, acc, lane, wm, wn);  // hi*hi
        mma_pass(sb + OFF_ALO, sb + OFF_BHI, acc, lane, wm, wn);  // lo*hi
        mma_pass(sb + OFF_AHI, sb + OFF_BLO, acc, lane, wm, wn);  // hi*lo
    }

    // Epilogue: combined scaled bias + relu, direct float2 stores.
    float2 bb[8];
#pragma unroll
    for (int nt = 0; nt < 8; nt++) {
        int c = wn * 64 + nt * 8 + (lane & 3) * 2;
        float v0 = bias0[c], v1 = bias0[c + 1];
        if (nrel > 1) { v0 += bias1[c]; v1 += bias1[c + 1]; }
        if (nrel > 2) { v0 += bias2[c]; v1 += bias2[c + 1]; }
        bb[nt].x = v0 * scale;
        bb[nt].y = v1 * scale;
    }
#pragma unroll
    for (int mt = 0; mt < 2; mt++) {
        int rbase = row0 + wm * 32 + mt * 16 + (lane >> 2);
#pragma unroll
        for (int half = 0; half < 2; half++) {
            int grow = rbase + half * 8;
            if (grow >= n_rows) continue;
            float* orow = obase + (size_t)grow * D;
#pragma unroll
            for (int nt = 0; nt < 8; nt++) {
                int c = wn * 64 + nt * 8 + (lane & 3) * 2;
                float2 v;
                v.x = fmaxf(acc[mt][nt][half * 2 + 0] + bb[nt].x, 0.f);
                v.y = fmaxf(acc[mt][nt][half * 2 + 1] + bb[nt].y, 0.f);
                *(float2*)(orow + c) = v;
            }
        }
    }
}

// ---------------------------------------------------------------------------
extern "C" void kernel_launch(void* const* d_in, const int* in_sizes, int n_in,
                              void* d_out, int out_size) {
    const float* node_feat = (const float*)d_in[0];
    const float* inst_feat = (const float*)d_in[1];
    const float* svc_feat  = (const float*)d_in[2];

    const int*   e_src[NREL];
    const int*   e_dst[NREL];
    const float* W[NREL];
    const float* B[NREL];
    for (int r = 0; r < NREL; r++) {
        e_src[r] = (const int*)  d_in[3 + r * 4 + 0];
        e_dst[r] = (const int*)  d_in[3 + r * 4 + 1];
        W[r]     = (const float*)d_in[3 + r * 4 + 2];
        B[r]     = (const float*)d_in[3 + r * 4 + 3];
    }

    float* out = (float*)d_out;

    static bool attr_set = false;
    if (!attr_set) {
        cudaFuncSetAttribute(tc_gemm_kernel,
                             cudaFuncAttributeMaxDynamicSharedMemorySize, SMEM_BYTES);
        attr_set = true;
    }

    // 1. zero counts
    zero_counts_kernel<<<512, 256>>>();

    // 2. build buckets + out-degrees
    build_kernel<<<(NREL * NEDGE + 255) / 256, 256>>>(
        e_src[0], e_dst[0], e_src[1], e_dst[1], e_src[2], e_dst[2],
        e_src[3], e_dst[3], e_src[4], e_dst[4], e_src[5], e_dst[5]);

    // 3. pre-split W tiles
    prep_w_kernel<<<NREL, 256>>>(W[0], W[1], W[2], W[3], W[4], W[5]);

    // 4. gather -> split-bf16 swizzled A tiles
    gather_all_kernel<<<NTILE * 16, 256>>>(
        svc_feat, inst_feat, node_feat, inst_feat, svc_feat, inst_feat);

    // 5. tensor-core GEMM (627 blocks)
    tc_gemm_kernel<<<627, 256, SMEM_BYTES>>>(
        B[0], B[1], B[2], B[3], B[4], B[5], out);
}